// round 1
// baseline (speedup 1.0000x reference)
#include <cuda_runtime.h>

#define B_   16
#define N_   1024
#define E_   1024
#define H_   16
#define D_   64
#define M_   (B_ * N_)        // 16384
#define QKV_N (3 * E_)        // 3072

// Scratch (allocation-free: __device__ globals)
static __device__ float g_q[(size_t)B_ * H_ * N_ * D_];   // 64 MB
static __device__ float g_k[(size_t)B_ * H_ * N_ * D_];   // 64 MB
static __device__ float g_v[(size_t)B_ * H_ * N_ * D_];   // 64 MB
static __device__ float g_o[(size_t)M_ * E_];             // 64 MB

// ---------------------------------------------------------------------------
// Kernel 1: QKV GEMM. C[M,3E] = x[M,E] @ W_qkv[E,3E] + b_qkv, scattered into
// g_q/g_k/g_v with [B,H,N,D] layout. Classic 128x128x8 SGEMM, 256 threads,
// 8x8 per-thread microtile in 2x2 blocks of float4.
// ---------------------------------------------------------------------------
__global__ __launch_bounds__(256) void qkv_gemm_kernel(
    const float* __restrict__ A, const float* __restrict__ W,
    const float* __restrict__ bias)
{
    __shared__ float As[8][132];   // k-major, padded (132*4 B = 16B aligned)
    __shared__ float Bs[8][128];

    const int tid = threadIdx.x;
    const int tx = tid & 15, ty = tid >> 4;
    const int m0 = blockIdx.y * 128, n0 = blockIdx.x * 128;

    const int arow = tid >> 1;          // 0..127
    const int acol = (tid & 1) << 2;    // 0 or 4
    const int brow = tid >> 5;          // 0..7
    const int bcol = (tid & 31) << 2;   // 0..124

    const float* Ap = A + (size_t)(m0 + arow) * E_ + acol;
    const float* Bp = W + (size_t)brow * QKV_N + (n0 + bcol);

    float acc[8][8];
#pragma unroll
    for (int i = 0; i < 8; i++)
#pragma unroll
        for (int j = 0; j < 8; j++) acc[i][j] = 0.f;

    for (int kt = 0; kt < E_; kt += 8) {
        float4 av = *(const float4*)(Ap + kt);
        float4 bv = *(const float4*)(Bp + (size_t)kt * QKV_N);
        As[acol + 0][arow] = av.x;
        As[acol + 1][arow] = av.y;
        As[acol + 2][arow] = av.z;
        As[acol + 3][arow] = av.w;
        *(float4*)&Bs[brow][bcol] = bv;
        __syncthreads();
#pragma unroll
        for (int k = 0; k < 8; k++) {
            float a[8], b[8];
            *(float4*)&a[0] = *(const float4*)&As[k][ty * 4];
            *(float4*)&a[4] = *(const float4*)&As[k][ty * 4 + 64];
            *(float4*)&b[0] = *(const float4*)&Bs[k][tx * 4];
            *(float4*)&b[4] = *(const float4*)&Bs[k][tx * 4 + 64];
#pragma unroll
            for (int i = 0; i < 8; i++)
#pragma unroll
                for (int j = 0; j < 8; j++)
                    acc[i][j] = fmaf(a[i], b[j], acc[i][j]);
        }
        __syncthreads();
    }

    // Epilogue: bias + scatter into q/k/v [B,H,N,D]. A 128-col tile never
    // crosses a q/k/v section boundary (3072/128 tiles, 1024 % 128 == 0).
#pragma unroll
    for (int ih = 0; ih < 2; ih++) {
#pragma unroll
        for (int ii = 0; ii < 4; ii++) {
            const int r  = m0 + ih * 64 + ty * 4 + ii;
            const int bb = r >> 10;
            const int nn = r & 1023;
#pragma unroll
            for (int jh = 0; jh < 2; jh++) {
                const int c   = n0 + jh * 64 + tx * 4;
                const int sec = c >> 10;          // 0:q 1:k 2:v
                const int e   = c & 1023;
                const int hh  = e >> 6;
                const int dd  = e & 63;
                float* dst = (sec == 0) ? g_q : (sec == 1) ? g_k : g_v;
                const size_t idx =
                    (((size_t)bb * H_ + hh) * N_ + nn) * D_ + dd;
                float4 v;
                v.x = acc[ih * 4 + ii][jh * 4 + 0] + bias[c + 0];
                v.y = acc[ih * 4 + ii][jh * 4 + 1] + bias[c + 1];
                v.z = acc[ih * 4 + ii][jh * 4 + 2] + bias[c + 2];
                v.w = acc[ih * 4 + ii][jh * 4 + 3] + bias[c + 3];
                *(float4*)&dst[idx] = v;
            }
        }
    }
}

// ---------------------------------------------------------------------------
// Kernel 2: flash attention, fp32. One CTA per (b, h, 64-row q tile).
// Q and K live d-major in smem with an XOR swizzle on the float4 column:
//   off(d, i) = d*64 + (((i>>2) ^ (d>>2)) << 2) + (i&3)
// -> conflict-free transpose stores and conflict-free float4 fragment reads,
// no padding needed. P tile reuses the K buffer. Total smem = 48 KB exactly.
// ---------------------------------------------------------------------------
__device__ __forceinline__ int qk_off(int d, int i) {
    return d * 64 + ((((i >> 2) ^ (d >> 2)) & 15) << 2) + (i & 3);
}
__device__ __forceinline__ int qk_off4(int d, int i4) {
    return d * 64 + (((i4 ^ (d >> 2)) & 15) << 2);
}

__global__ __launch_bounds__(256) void attn_kernel()
{
    __shared__ float sQ[64 * 64];   // swizzled, d-major
    __shared__ float sKP[64 * 64];  // K tile (swizzled, d-major), reused as P^T
    __shared__ float sV[64 * 64];   // row-major [kv][d]

    const int tid = threadIdx.x;
    const int tx = tid & 15, ty = tid >> 4;
    const int q0 = blockIdx.x * 64;
    const int h  = blockIdx.y;
    const int b  = blockIdx.z;

    const size_t head_base = (size_t)(b * H_ + h) * N_ * D_;
    const float* qb = g_q + head_base;
    const float* kb = g_k + head_base;
    const float* vb = g_v + head_base;

    // Load Q tile, transposed into swizzled d-major layout
#pragma unroll
    for (int p = 0; p < 4; p++) {
        const int idx = p * 256 + tid;       // 0..1023 float4 slots
        const int row = idx >> 4;            // 0..63 (query)
        const int c4  = (idx & 15) << 2;     // 0..60 (d)
        float4 v = *(const float4*)(qb + (size_t)(q0 + row) * D_ + c4);
        sQ[qk_off(c4 + 0, row)] = v.x;
        sQ[qk_off(c4 + 1, row)] = v.y;
        sQ[qk_off(c4 + 2, row)] = v.z;
        sQ[qk_off(c4 + 3, row)] = v.w;
    }

    float m_r[4], l_r[4], o[4][4];
#pragma unroll
    for (int i = 0; i < 4; i++) {
        m_r[i] = -1e30f; l_r[i] = 0.f;
#pragma unroll
        for (int j = 0; j < 4; j++) o[i][j] = 0.f;
    }
    const float scale = 0.125f;  // D^-0.5

    for (int t = 0; t < 16; t++) {
        __syncthreads();  // prior-iter readers of sKP/sV done
        // Load K (transposed+swizzled) and V (row-major)
#pragma unroll
        for (int p = 0; p < 4; p++) {
            const int idx = p * 256 + tid;
            const int row = idx >> 4;
            const int c4  = (idx & 15) << 2;
            const size_t g = (size_t)(t * 64 + row) * D_ + c4;
            float4 kv = *(const float4*)(kb + g);
            sKP[qk_off(c4 + 0, row)] = kv.x;
            sKP[qk_off(c4 + 1, row)] = kv.y;
            sKP[qk_off(c4 + 2, row)] = kv.z;
            sKP[qk_off(c4 + 3, row)] = kv.w;
            *(float4*)&sV[row * 64 + c4] = *(const float4*)(vb + g);
        }
        __syncthreads();

        // S = Q K^T for this tile (4x4 frag per thread)
        float s[4][4];
#pragma unroll
        for (int i = 0; i < 4; i++)
#pragma unroll
            for (int j = 0; j < 4; j++) s[i][j] = 0.f;

#pragma unroll 4
        for (int d = 0; d < 64; d++) {
            float4 aq = *(const float4*)&sQ[qk_off4(d, ty)];
            float4 bk = *(const float4*)&sKP[qk_off4(d, tx)];
            const float a[4] = {aq.x, aq.y, aq.z, aq.w};
            const float bb2[4] = {bk.x, bk.y, bk.z, bk.w};
#pragma unroll
            for (int i = 0; i < 4; i++)
#pragma unroll
                for (int j = 0; j < 4; j++)
                    s[i][j] = fmaf(a[i], bb2[j], s[i][j]);
        }

        // Online softmax per row (16-lane shfl groups: lanes 0-15 / 16-31)
#pragma unroll
        for (int i = 0; i < 4; i++) {
            float mx = -1e30f;
#pragma unroll
            for (int j = 0; j < 4; j++) {
                s[i][j] *= scale;
                mx = fmaxf(mx, s[i][j]);
            }
#pragma unroll
            for (int off = 8; off > 0; off >>= 1)
                mx = fmaxf(mx, __shfl_xor_sync(0xffffffffu, mx, off));
            const float mnew  = fmaxf(m_r[i], mx);
            const float alpha = __expf(m_r[i] - mnew);
            float rs = 0.f;
#pragma unroll
            for (int j = 0; j < 4; j++) {
                s[i][j] = __expf(s[i][j] - mnew);
                rs += s[i][j];
            }
#pragma unroll
            for (int off = 8; off > 0; off >>= 1)
                rs += __shfl_xor_sync(0xffffffffu, rs, off);
            l_r[i] = l_r[i] * alpha + rs;
            m_r[i] = mnew;
#pragma unroll
            for (int c = 0; c < 4; c++) o[i][c] *= alpha;
        }

        __syncthreads();  // everyone done reading K before P overwrites it
        // Write P^T into sKP (kv-major, same swizzle): row j = tx*4+jj
#pragma unroll
        for (int jj = 0; jj < 4; jj++) {
            const int j = tx * 4 + jj;
            float4 v;
            v.x = s[0][jj]; v.y = s[1][jj]; v.z = s[2][jj]; v.w = s[3][jj];
            *(float4*)&sKP[qk_off4(j, ty)] = v;
        }
        __syncthreads();

        // O += P V
#pragma unroll 4
        for (int j = 0; j < 64; j++) {
            float4 ap = *(const float4*)&sKP[qk_off4(j, ty)];
            float4 bv = *(const float4*)&sV[j * 64 + tx * 4];
            const float a[4] = {ap.x, ap.y, ap.z, ap.w};
            const float vv[4] = {bv.x, bv.y, bv.z, bv.w};
#pragma unroll
            for (int i = 0; i < 4; i++)
#pragma unroll
                for (int c = 0; c < 4; c++)
                    o[i][c] = fmaf(a[i], vv[c], o[i][c]);
        }
    }

    // Epilogue: normalize and write to g_o [B, N, E]
#pragma unroll
    for (int i = 0; i < 4; i++) {
        const float inv = 1.f / l_r[i];
        const int row = q0 + ty * 4 + i;
        float4 v;
        v.x = o[i][0] * inv; v.y = o[i][1] * inv;
        v.z = o[i][2] * inv; v.w = o[i][3] * inv;
        float* dst = g_o + ((size_t)b * N_ + row) * E_ + h * 64 + tx * 4;
        *(float4*)dst = v;
    }
}

// ---------------------------------------------------------------------------
// Kernel 3: output projection. out[M,E] = g_o[M,E] @ W_proj[E,E] + b_proj.
// Same 128x128x8 SGEMM, straight store.
// ---------------------------------------------------------------------------
__global__ __launch_bounds__(256) void proj_gemm_kernel(
    const float* __restrict__ W, const float* __restrict__ bias,
    float* __restrict__ out)
{
    __shared__ float As[8][132];
    __shared__ float Bs[8][128];

    const int tid = threadIdx.x;
    const int tx = tid & 15, ty = tid >> 4;
    const int m0 = blockIdx.y * 128, n0 = blockIdx.x * 128;

    const int arow = tid >> 1;
    const int acol = (tid & 1) << 2;
    const int brow = tid >> 5;
    const int bcol = (tid & 31) << 2;

    const float* Ap = g_o + (size_t)(m0 + arow) * E_ + acol;
    const float* Bp = W + (size_t)brow * E_ + (n0 + bcol);

    float acc[8][8];
#pragma unroll
    for (int i = 0; i < 8; i++)
#pragma unroll
        for (int j = 0; j < 8; j++) acc[i][j] = 0.f;

    for (int kt = 0; kt < E_; kt += 8) {
        float4 av = *(const float4*)(Ap + kt);
        float4 bv = *(const float4*)(Bp + (size_t)kt * E_);
        As[acol + 0][arow] = av.x;
        As[acol + 1][arow] = av.y;
        As[acol + 2][arow] = av.z;
        As[acol + 3][arow] = av.w;
        *(float4*)&Bs[brow][bcol] = bv;
        __syncthreads();
#pragma unroll
        for (int k = 0; k < 8; k++) {
            float a[8], b[8];
            *(float4*)&a[0] = *(const float4*)&As[k][ty * 4];
            *(float4*)&a[4] = *(const float4*)&As[k][ty * 4 + 64];
            *(float4*)&b[0] = *(const float4*)&Bs[k][tx * 4];
            *(float4*)&b[4] = *(const float4*)&Bs[k][tx * 4 + 64];
#pragma unroll
            for (int i = 0; i < 8; i++)
#pragma unroll
                for (int j = 0; j < 8; j++)
                    acc[i][j] = fmaf(a[i], b[j], acc[i][j]);
        }
        __syncthreads();
    }

#pragma unroll
    for (int ih = 0; ih < 2; ih++) {
#pragma unroll
        for (int ii = 0; ii < 4; ii++) {
            const int r = m0 + ih * 64 + ty * 4 + ii;
#pragma unroll
            for (int jh = 0; jh < 2; jh++) {
                const int c = n0 + jh * 64 + tx * 4;
                float4 v;
                v.x = acc[ih * 4 + ii][jh * 4 + 0] + bias[c + 0];
                v.y = acc[ih * 4 + ii][jh * 4 + 1] + bias[c + 1];
                v.z = acc[ih * 4 + ii][jh * 4 + 2] + bias[c + 2];
                v.w = acc[ih * 4 + ii][jh * 4 + 3] + bias[c + 3];
                *(float4*)&out[(size_t)r * E_ + c] = v;
            }
        }
    }
}

// ---------------------------------------------------------------------------
extern "C" void kernel_launch(void* const* d_in, const int* in_sizes, int n_in,
                              void* d_out, int out_size)
{
    const float* x  = (const float*)d_in[0];   // [B,N,E]
    const float* Wq = (const float*)d_in[1];   // [E,3E]
    const float* bq = (const float*)d_in[2];   // [3E]
    const float* Wp = (const float*)d_in[3];   // [E,E]
    const float* bp = (const float*)d_in[4];   // [E]
    float* out = (float*)d_out;                // [B,N,E]

    dim3 g1(QKV_N / 128, M_ / 128);            // (24, 128)
    qkv_gemm_kernel<<<g1, 256>>>(x, Wq, bq);

    dim3 g2(N_ / 64, H_, B_);                  // (16, 16, 16)
    attn_kernel<<<g2, 256>>>();

    dim3 g3(E_ / 128, M_ / 128);               // (8, 128)
    proj_gemm_kernel<<<g3, 256>>>(Wp, bp, out);
}

// round 3
// speedup vs baseline: 1.6501x; 1.6501x over previous
#include <cuda_runtime.h>
#include <cuda_bf16.h>
#include <cstdint>

#define B_   16
#define N_   1024
#define E_   1024
#define H_   16
#define D_   64
#define M_   (B_ * N_)        // 16384
#define QKV_N (3 * E_)        // 3072
#define KPP_  (3 * E_)        // tripled K'' = 3072
#define KT_   (KPP_ / 64)     // 48 k-iters of 64

// ---------------------------------------------------------------------------
// Scratch (__device__ globals; no allocations anywhere)
// ---------------------------------------------------------------------------
static __device__ __align__(1024) float g_q[(size_t)B_ * H_ * N_ * D_];
static __device__ __align__(1024) float g_k[(size_t)B_ * H_ * N_ * D_];
static __device__ __align__(1024) float g_v[(size_t)B_ * H_ * N_ * D_];
static __device__ __align__(1024) float g_o[(size_t)M_ * E_];
// A'' [M][3072] row-major bf16 (reused for x and for attention output)
static __device__ __align__(1024) __nv_bfloat16 g_at [(size_t)M_ * KPP_];
// W'' [n][3072] bf16 (n-major, i.e. transposed weights, k contiguous)
static __device__ __align__(1024) __nv_bfloat16 g_wqt[(size_t)QKV_N * KPP_];
static __device__ __align__(1024) __nv_bfloat16 g_wpt[(size_t)E_ * KPP_];

// ---------------------------------------------------------------------------
// helpers
// ---------------------------------------------------------------------------
__device__ __forceinline__ uint32_t smem_u32(const void* p) {
    uint32_t a;
    asm("{ .reg .u64 t; cvta.to.shared.u64 t, %1; cvt.u32.u64 %0, t; }"
        : "=r"(a) : "l"(p));
    return a;
}
__device__ __forceinline__ void cp_async16(uint32_t dst, const void* src) {
    asm volatile("cp.async.cg.shared.global [%0], [%1], 16;"
                 :: "r"(dst), "l"(src));
}
__device__ __forceinline__ void cp_commit() {
    asm volatile("cp.async.commit_group;" ::: "memory");
}
__device__ __forceinline__ void ldmatrix_x4(uint32_t* d, uint32_t addr) {
    asm volatile("ldmatrix.sync.aligned.m8n8.x4.shared.b16 {%0,%1,%2,%3}, [%4];"
                 : "=r"(d[0]), "=r"(d[1]), "=r"(d[2]), "=r"(d[3]) : "r"(addr));
}
__device__ __forceinline__ void mma16816(float* c, const uint32_t* a,
                                         uint32_t b0, uint32_t b1) {
    asm volatile(
        "mma.sync.aligned.m16n8k16.row.col.f32.bf16.bf16.f32 "
        "{%0,%1,%2,%3}, {%4,%5,%6,%7}, {%8,%9}, {%0,%1,%2,%3};"
        : "+f"(c[0]), "+f"(c[1]), "+f"(c[2]), "+f"(c[3])
        : "r"(a[0]), "r"(a[1]), "r"(a[2]), "r"(a[3]), "r"(b0), "r"(b1));
}

// packed f32x2 (attention)
__device__ __forceinline__ unsigned long long pk2(float x, float y) {
    unsigned long long r;
    asm("mov.b64 %0, {%1, %2};" : "=l"(r) : "f"(x), "f"(y));
    return r;
}
__device__ __forceinline__ void unpk2(unsigned long long v, float& x, float& y) {
    asm("mov.b64 {%0, %1}, %2;" : "=f"(x), "=f"(y) : "l"(v));
}
__device__ __forceinline__ unsigned long long fma2(
    unsigned long long a, unsigned long long b, unsigned long long c) {
    unsigned long long d;
    asm("fma.rn.f32x2 %0, %1, %2, %3;" : "=l"(d) : "l"(a), "l"(b), "l"(c));
    return d;
}
__device__ __forceinline__ unsigned long long mul2(
    unsigned long long a, unsigned long long b) {
    unsigned long long d;
    asm("mul.rn.f32x2 %0, %1, %2;" : "=l"(d) : "l"(a), "l"(b));
    return d;
}

// ---------------------------------------------------------------------------
// conv_a: fp32 [M,1024] (x or g_o) -> A'' [M][Ah | Al | Ah] bf16 row-major
// ---------------------------------------------------------------------------
__global__ __launch_bounds__(256) void conv_a_kernel(
    const float* __restrict__ src_in, int use_go)
{
    const float* src = use_go ? g_o : src_in;
    const int m  = blockIdx.x;
    const int k4 = threadIdx.x << 2;
    float4 v = *(const float4*)(src + (size_t)m * E_ + k4);
    const float f[4] = {v.x, v.y, v.z, v.w};

    uint32_t hi01, hi23, lo01, lo23;
    {
        __nv_bfloat16 h0 = __float2bfloat16_rn(f[0]);
        __nv_bfloat16 h1 = __float2bfloat16_rn(f[1]);
        __nv_bfloat16 h2 = __float2bfloat16_rn(f[2]);
        __nv_bfloat16 h3 = __float2bfloat16_rn(f[3]);
        __nv_bfloat16 l0 = __float2bfloat16_rn(f[0] - __bfloat162float(h0));
        __nv_bfloat16 l1 = __float2bfloat16_rn(f[1] - __bfloat162float(h1));
        __nv_bfloat16 l2 = __float2bfloat16_rn(f[2] - __bfloat162float(h2));
        __nv_bfloat16 l3 = __float2bfloat16_rn(f[3] - __bfloat162float(h3));
        hi01 = (uint32_t)__bfloat16_as_ushort(h0) | ((uint32_t)__bfloat16_as_ushort(h1) << 16);
        hi23 = (uint32_t)__bfloat16_as_ushort(h2) | ((uint32_t)__bfloat16_as_ushort(h3) << 16);
        lo01 = (uint32_t)__bfloat16_as_ushort(l0) | ((uint32_t)__bfloat16_as_ushort(l1) << 16);
        lo23 = (uint32_t)__bfloat16_as_ushort(l2) | ((uint32_t)__bfloat16_as_ushort(l3) << 16);
    }

    const size_t rb = (size_t)m * KPP_;
    uint2 hi; hi.x = hi01; hi.y = hi23;
    uint2 lo; lo.x = lo01; lo.y = lo23;
    *(uint2*)&g_at[rb + k4]        = hi;
    *(uint2*)&g_at[rb + 1024 + k4] = lo;
    *(uint2*)&g_at[rb + 2048 + k4] = hi;
}

// ---------------------------------------------------------------------------
// conv_w: W [1024][Ncols] fp32 -> W'' [n][Bh | Bh | Bl] bf16 (k contiguous)
// One thread per (n, 4-k group). Scattered 4B reads, coalesced 8B writes.
// ---------------------------------------------------------------------------
__global__ __launch_bounds__(256) void conv_w_kernel(
    const float* __restrict__ W, int Ncols, int which)
{
    __nv_bfloat16* dst = which ? g_wpt : g_wqt;
    const int idx = blockIdx.x * 256 + threadIdx.x;
    const int n  = idx >> 8;
    const int k  = (idx & 255) << 2;
    if (n >= Ncols) return;

    float f[4];
#pragma unroll
    for (int j = 0; j < 4; j++)
        f[j] = W[(size_t)(k + j) * Ncols + n];

    uint32_t hi01, hi23, lo01, lo23;
    {
        __nv_bfloat16 h0 = __float2bfloat16_rn(f[0]);
        __nv_bfloat16 h1 = __float2bfloat16_rn(f[1]);
        __nv_bfloat16 h2 = __float2bfloat16_rn(f[2]);
        __nv_bfloat16 h3 = __float2bfloat16_rn(f[3]);
        __nv_bfloat16 l0 = __float2bfloat16_rn(f[0] - __bfloat162float(h0));
        __nv_bfloat16 l1 = __float2bfloat16_rn(f[1] - __bfloat162float(h1));
        __nv_bfloat16 l2 = __float2bfloat16_rn(f[2] - __bfloat162float(h2));
        __nv_bfloat16 l3 = __float2bfloat16_rn(f[3] - __bfloat162float(h3));
        hi01 = (uint32_t)__bfloat16_as_ushort(h0) | ((uint32_t)__bfloat16_as_ushort(h1) << 16);
        hi23 = (uint32_t)__bfloat16_as_ushort(h2) | ((uint32_t)__bfloat16_as_ushort(h3) << 16);
        lo01 = (uint32_t)__bfloat16_as_ushort(l0) | ((uint32_t)__bfloat16_as_ushort(l1) << 16);
        lo23 = (uint32_t)__bfloat16_as_ushort(l2) | ((uint32_t)__bfloat16_as_ushort(l3) << 16);
    }

    const size_t rb = (size_t)n * KPP_;
    uint2 hi; hi.x = hi01; hi.y = hi23;
    uint2 lo; lo.x = lo01; lo.y = lo23;
    *(uint2*)&dst[rb + k]        = hi;
    *(uint2*)&dst[rb + 1024 + k] = hi;
    *(uint2*)&dst[rb + 2048 + k] = lo;
}

// ---------------------------------------------------------------------------
// HMMA GEMM: C[M, Ncols] = A''[M,3072] @ W''^T + bias
// CTA 128x128, K-step 64, 8 warps (2x4), warp tile 64x32, 3-stage cp.async.
// Smem rows are 128B; chunk-XOR swizzle -> conflict-free ldmatrix.
// mode 0: scatter into g_q/g_k/g_v ([B,H,N,D]); mode 1: write out[M,E].
// ---------------------------------------------------------------------------
#define GEMM_SMEM (3 * 32768)

__device__ __forceinline__ void load_tile(
    uint32_t sbase, int stage, int ktile,
    const __nv_bfloat16* A, const __nv_bfloat16* Bt,
    int m0, int n0, int tid)
{
    const char* aSrc = (const char*)(A  + (size_t)m0 * KPP_ + ktile * 64);
    const char* bSrc = (const char*)(Bt + (size_t)n0 * KPP_ + ktile * 64);
    const uint32_t sa = sbase + stage * 32768;
    const uint32_t sbB = sa + 16384;
#pragma unroll
    for (int i = 0; i < 4; i++) {
        const int u = i * 256 + tid;
        const int r = u >> 3, c = u & 7;
        cp_async16(sa + r * 128 + ((c ^ (r & 7)) << 4),
                   aSrc + (size_t)r * (KPP_ * 2) + c * 16);
    }
#pragma unroll
    for (int i = 0; i < 4; i++) {
        const int u = i * 256 + tid;
        const int r = u >> 3, c = u & 7;
        cp_async16(sbB + r * 128 + ((c ^ (r & 7)) << 4),
                   bSrc + (size_t)r * (KPP_ * 2) + c * 16);
    }
    cp_commit();
}

__global__ __launch_bounds__(256) void hmma_gemm_kernel(
    const float* __restrict__ bias, float* __restrict__ out, int mode)
{
    extern __shared__ char smem[];
    const uint32_t sb = smem_u32(smem);

    const __nv_bfloat16* A  = g_at;
    const __nv_bfloat16* Bt = (mode == 0) ? g_wqt : g_wpt;

    const int tid  = threadIdx.x;
    const int lane = tid & 31, wid = tid >> 5;
    const int warp_m = wid & 1, warp_n = wid >> 1;
    const int m0 = blockIdx.y * 128, n0 = blockIdx.x * 128;

    float acc[4][4][4];
#pragma unroll
    for (int i = 0; i < 4; i++)
#pragma unroll
        for (int j = 0; j < 4; j++)
#pragma unroll
            for (int r = 0; r < 4; r++) acc[i][j][r] = 0.f;

    load_tile(sb, 0, 0, A, Bt, m0, n0, tid);
    load_tile(sb, 1, 1, A, Bt, m0, n0, tid);

    const int lane15 = lane & 15, lhalf = lane >> 4;

    for (int kt = 0; kt < KT_; kt++) {
        if (kt + 2 < KT_)
            load_tile(sb, (kt + 2) % 3, kt + 2, A, Bt, m0, n0, tid);
        else
            cp_commit();  // keep group counting uniform
        asm volatile("cp.async.wait_group 2;" ::: "memory");
        __syncthreads();

        const uint32_t sa  = sb + (kt % 3) * 32768;
        const uint32_t sbB = sa + 16384;
#pragma unroll
        for (int kk = 0; kk < 4; kk++) {
            const int kc = kk * 2 + lhalf;  // 16B chunk index along k
            uint32_t a[4][4];
#pragma unroll
            for (int mi = 0; mi < 4; mi++) {
                const int r = warp_m * 64 + mi * 16 + lane15;
                ldmatrix_x4(a[mi], sa + r * 128 + ((kc ^ (r & 7)) << 4));
            }
            uint32_t bf[2][4];
#pragma unroll
            for (int ng = 0; ng < 2; ng++) {
                const int r = warp_n * 32 + ng * 16 + lane15;
                ldmatrix_x4(bf[ng], sbB + r * 128 + ((kc ^ (r & 7)) << 4));
            }
#pragma unroll
            for (int mi = 0; mi < 4; mi++)
#pragma unroll
                for (int nj = 0; nj < 4; nj++)
                    mma16816(acc[mi][nj], a[mi],
                             bf[nj >> 1][nj & 1], bf[nj >> 1][(nj & 1) + 2]);
        }
        __syncthreads();
    }

    // Epilogue
    const int mrow = m0 + warp_m * 64 + (lane >> 2);
    const int ncb  = n0 + warp_n * 32 + (lane & 3) * 2;
#pragma unroll
    for (int mi = 0; mi < 4; mi++) {
#pragma unroll
        for (int nj = 0; nj < 4; nj++) {
            const int c  = ncb + nj * 8;
            const float b0 = bias[c], b1 = bias[c + 1];
            const int r0 = mrow + mi * 16;
            float2 v0; v0.x = acc[mi][nj][0] + b0; v0.y = acc[mi][nj][1] + b1;
            float2 v1; v1.x = acc[mi][nj][2] + b0; v1.y = acc[mi][nj][3] + b1;
            if (mode == 0) {
                const int sec = c >> 10, e = c & 1023;
                const int hh = e >> 6, dd = e & 63;
                float* base = (sec == 0) ? g_q : (sec == 1) ? g_k : g_v;
                {
                    const int bb = r0 >> 10, nn = r0 & 1023;
                    *(float2*)&base[(((size_t)bb * H_ + hh) * N_ + nn) * D_ + dd] = v0;
                }
                {
                    const int r1 = r0 + 8;
                    const int bb = r1 >> 10, nn = r1 & 1023;
                    *(float2*)&base[(((size_t)bb * H_ + hh) * N_ + nn) * D_ + dd] = v1;
                }
            } else {
                *(float2*)&out[(size_t)r0 * E_ + c] = v0;
                *(float2*)&out[(size_t)(r0 + 8) * E_ + c] = v1;
            }
        }
    }
}

// ---------------------------------------------------------------------------
// Flash attention, fp32 with packed f32x2 inner products (unchanged R1 logic).
// ---------------------------------------------------------------------------
__device__ __forceinline__ int qk_off(int d, int i) {
    return d * 64 + ((((i >> 2) ^ (d >> 2)) & 15) << 2) + (i & 3);
}
__device__ __forceinline__ int qk_off4(int d, int i4) {
    return d * 64 + (((i4 ^ (d >> 2)) & 15) << 2);
}

__global__ __launch_bounds__(256) void attn_kernel()
{
    __shared__ float sQ[64 * 64];
    __shared__ float sKP[64 * 64];
    __shared__ float sV[64 * 64];

    const int tid = threadIdx.x;
    const int tx = tid & 15, ty = tid >> 4;
    const int q0 = blockIdx.x * 64;
    const int h  = blockIdx.y;
    const int b  = blockIdx.z;

    const size_t head_base = (size_t)(b * H_ + h) * N_ * D_;
    const float* qb = g_q + head_base;
    const float* kb = g_k + head_base;
    const float* vb = g_v + head_base;

#pragma unroll
    for (int p = 0; p < 4; p++) {
        const int idx = p * 256 + tid;
        const int row = idx >> 4;
        const int c4  = (idx & 15) << 2;
        float4 v = *(const float4*)(qb + (size_t)(q0 + row) * D_ + c4);
        sQ[qk_off(c4 + 0, row)] = v.x;
        sQ[qk_off(c4 + 1, row)] = v.y;
        sQ[qk_off(c4 + 2, row)] = v.z;
        sQ[qk_off(c4 + 3, row)] = v.w;
    }

    float m_r[4], l_r[4];
    unsigned long long o2[4][2];
#pragma unroll
    for (int i = 0; i < 4; i++) {
        m_r[i] = -1e30f; l_r[i] = 0.f;
        o2[i][0] = 0ull; o2[i][1] = 0ull;
    }
    const float scale = 0.125f;

    for (int t = 0; t < 16; t++) {
        __syncthreads();
#pragma unroll
        for (int p = 0; p < 4; p++) {
            const int idx = p * 256 + tid;
            const int row = idx >> 4;
            const int c4  = (idx & 15) << 2;
            const size_t g = (size_t)(t * 64 + row) * D_ + c4;
            float4 kv = *(const float4*)(kb + g);
            sKP[qk_off(c4 + 0, row)] = kv.x;
            sKP[qk_off(c4 + 1, row)] = kv.y;
            sKP[qk_off(c4 + 2, row)] = kv.z;
            sKP[qk_off(c4 + 3, row)] = kv.w;
            *(float4*)&sV[row * 64 + c4] = *(const float4*)(vb + g);
        }
        __syncthreads();

        unsigned long long s2[4][2];
#pragma unroll
        for (int i = 0; i < 4; i++) { s2[i][0] = 0ull; s2[i][1] = 0ull; }

#pragma unroll 4
        for (int d = 0; d < 64; d++) {
            float4 aq = *(const float4*)&sQ[qk_off4(d, ty)];
            float4 bk = *(const float4*)&sKP[qk_off4(d, tx)];
            const unsigned long long b0 = pk2(bk.x, bk.y), b1 = pk2(bk.z, bk.w);
            const unsigned long long a0 = pk2(aq.x, aq.x), a1 = pk2(aq.y, aq.y);
            const unsigned long long a2 = pk2(aq.z, aq.z), a3 = pk2(aq.w, aq.w);
            s2[0][0] = fma2(a0, b0, s2[0][0]); s2[0][1] = fma2(a0, b1, s2[0][1]);
            s2[1][0] = fma2(a1, b0, s2[1][0]); s2[1][1] = fma2(a1, b1, s2[1][1]);
            s2[2][0] = fma2(a2, b0, s2[2][0]); s2[2][1] = fma2(a2, b1, s2[2][1]);
            s2[3][0] = fma2(a3, b0, s2[3][0]); s2[3][1] = fma2(a3, b1, s2[3][1]);
        }

        float s[4][4];
#pragma unroll
        for (int i = 0; i < 4; i++) {
            unpk2(s2[i][0], s[i][0], s[i][1]);
            unpk2(s2[i][1], s[i][2], s[i][3]);
        }

#pragma unroll
        for (int i = 0; i < 4; i++) {
            float mx = -1e30f;
#pragma unroll
            for (int j = 0; j < 4; j++) {
                s[i][j] *= scale;
                mx = fmaxf(mx, s[i][j]);
            }
#pragma unroll
            for (int off = 8; off > 0; off >>= 1)
                mx = fmaxf(mx, __shfl_xor_sync(0xffffffffu, mx, off));
            const float mnew  = fmaxf(m_r[i], mx);
            const float alpha = __expf(m_r[i] - mnew);
            float rs = 0.f;
#pragma unroll
            for (int j = 0; j < 4; j++) {
                s[i][j] = __expf(s[i][j] - mnew);
                rs += s[i][j];
            }
#pragma unroll
            for (int off = 8; off > 0; off >>= 1)
                rs += __shfl_xor_sync(0xffffffffu, rs, off);
            l_r[i] = l_r[i] * alpha + rs;
            m_r[i] = mnew;
            const unsigned long long al2 = pk2(alpha, alpha);
            o2[i][0] = mul2(o2[i][0], al2);
            o2[i][1] = mul2(o2[i][1], al2);
        }

        __syncthreads();
#pragma unroll
        for (int jj = 0; jj < 4; jj++) {
            const int j = tx * 4 + jj;
            float4 v;
            v.x = s[0][jj]; v.y = s[1][jj]; v.z = s[2][jj]; v.w = s[3][jj];
            *(float4*)&sKP[qk_off4(j, ty)] = v;
        }
        __syncthreads();

#pragma unroll 4
        for (int j = 0; j < 64; j++) {
            float4 ap = *(const float4*)&sKP[qk_off4(j, ty)];
            float4 bv = *(const float4*)&sV[j * 64 + tx * 4];
            const unsigned long long v0 = pk2(bv.x, bv.y), v1 = pk2(bv.z, bv.w);
            const unsigned long long a0 = pk2(ap.x, ap.x), a1 = pk2(ap.y, ap.y);
            const unsigned long long a2 = pk2(ap.z, ap.z), a3 = pk2(ap.w, ap.w);
            o2[0][0] = fma2(a0, v0, o2[0][0]); o2[0][1] = fma2(a0, v1, o2[0][1]);
            o2[1][0] = fma2(a1, v0, o2[1][0]); o2[1][1] = fma2(a1, v1, o2[1][1]);
            o2[2][0] = fma2(a2, v0, o2[2][0]); o2[2][1] = fma2(a2, v1, o2[2][1]);
            o2[3][0] = fma2(a3, v0, o2[3][0]); o2[3][1] = fma2(a3, v1, o2[3][1]);
        }
    }

#pragma unroll
    for (int i = 0; i < 4; i++) {
        const float inv = 1.f / l_r[i];
        const int row = q0 + ty * 4 + i;
        float o[4];
        unpk2(o2[i][0], o[0], o[1]);
        unpk2(o2[i][1], o[2], o[3]);
        float4 v;
        v.x = o[0] * inv; v.y = o[1] * inv; v.z = o[2] * inv; v.w = o[3] * inv;
        float* dst = g_o + ((size_t)b * N_ + row) * E_ + h * 64 + tx * 4;
        *(float4*)dst = v;
    }
}

// ---------------------------------------------------------------------------
extern "C" void kernel_launch(void* const* d_in, const int* in_sizes, int n_in,
                              void* d_out, int out_size)
{
    const float* x  = (const float*)d_in[0];   // [B,N,E]
    const float* Wq = (const float*)d_in[1];   // [E,3E]
    const float* bq = (const float*)d_in[2];   // [3E]
    const float* Wp = (const float*)d_in[3];   // [E,E]
    const float* bp = (const float*)d_in[4];   // [E]
    float* out = (float*)d_out;                // [B,N,E]

    cudaFuncSetAttribute(hmma_gemm_kernel,
                         cudaFuncAttributeMaxDynamicSharedMemorySize, GEMM_SMEM);

    // 1. conversions
    conv_a_kernel<<<M_, 256>>>(x, 0);
    conv_w_kernel<<<QKV_N, 256>>>(Wq, QKV_N, 0);
    conv_w_kernel<<<E_, 256>>>(Wp, E_, 1);

    // 2. QKV GEMM (HMMA), scatter into g_q/g_k/g_v
    hmma_gemm_kernel<<<dim3(QKV_N / 128, M_ / 128), 256, GEMM_SMEM>>>(bq, out, 0);

    // 3. attention (fp32, packed f32x2)
    attn_kernel<<<dim3(N_ / 64, H_, B_), 256>>>();

    // 4. attn output -> A'', then projection GEMM
    conv_a_kernel<<<M_, 256>>>(nullptr, 1);
    hmma_gemm_kernel<<<dim3(E_ / 128, M_ / 128), 256, GEMM_SMEM>>>(bp, out, 1);
}

// round 4
// speedup vs baseline: 2.6988x; 1.6356x over previous
#include <cuda_runtime.h>
#include <cuda_bf16.h>
#include <cstdint>

#define B_   16
#define N_   1024
#define E_   1024
#define H_   16
#define D_   64
#define M_   (B_ * N_)        // 16384
#define QKV_N (3 * E_)        // 3072
#define KPP_  (3 * E_)        // tripled K'' = 3072
#define KT_   (KPP_ / 64)     // 48 k-iters of 64

// ---------------------------------------------------------------------------
// Scratch (__device__ globals; no allocations anywhere)
// ---------------------------------------------------------------------------
// bf16 hi/lo Q,K in [B,H,N,D]; V transposed in [B,H,D,N]
static __device__ __align__(1024) __nv_bfloat16 g_qh[(size_t)B_ * H_ * N_ * D_];
static __device__ __align__(1024) __nv_bfloat16 g_ql[(size_t)B_ * H_ * N_ * D_];
static __device__ __align__(1024) __nv_bfloat16 g_kh[(size_t)B_ * H_ * N_ * D_];
static __device__ __align__(1024) __nv_bfloat16 g_kl[(size_t)B_ * H_ * N_ * D_];
static __device__ __align__(1024) __nv_bfloat16 g_vth[(size_t)B_ * H_ * D_ * N_];
static __device__ __align__(1024) __nv_bfloat16 g_vtl[(size_t)B_ * H_ * D_ * N_];
// A'' [M][3072] row-major bf16 (x for QKV GEMM; attn output for proj GEMM)
static __device__ __align__(1024) __nv_bfloat16 g_at [(size_t)M_ * KPP_];
// W'' [n][3072] bf16 (n-major: transposed weights, k contiguous)
static __device__ __align__(1024) __nv_bfloat16 g_wqt[(size_t)QKV_N * KPP_];
static __device__ __align__(1024) __nv_bfloat16 g_wpt[(size_t)E_ * KPP_];

// ---------------------------------------------------------------------------
// helpers
// ---------------------------------------------------------------------------
__device__ __forceinline__ uint32_t smem_u32(const void* p) {
    uint32_t a;
    asm("{ .reg .u64 t; cvta.to.shared.u64 t, %1; cvt.u32.u64 %0, t; }"
        : "=r"(a) : "l"(p));
    return a;
}
__device__ __forceinline__ void cp_async16(uint32_t dst, const void* src) {
    asm volatile("cp.async.cg.shared.global [%0], [%1], 16;"
                 :: "r"(dst), "l"(src));
}
__device__ __forceinline__ void cp_commit() {
    asm volatile("cp.async.commit_group;" ::: "memory");
}
__device__ __forceinline__ void ldmatrix_x4(uint32_t* d, uint32_t addr) {
    asm volatile("ldmatrix.sync.aligned.m8n8.x4.shared.b16 {%0,%1,%2,%3}, [%4];"
                 : "=r"(d[0]), "=r"(d[1]), "=r"(d[2]), "=r"(d[3]) : "r"(addr));
}
__device__ __forceinline__ void mma16816(float* c, const uint32_t* a,
                                         uint32_t b0, uint32_t b1) {
    asm volatile(
        "mma.sync.aligned.m16n8k16.row.col.f32.bf16.bf16.f32 "
        "{%0,%1,%2,%3}, {%4,%5,%6,%7}, {%8,%9}, {%0,%1,%2,%3};"
        : "+f"(c[0]), "+f"(c[1]), "+f"(c[2]), "+f"(c[3])
        : "r"(a[0]), "r"(a[1]), "r"(a[2]), "r"(a[3]), "r"(b0), "r"(b1));
}
__device__ __forceinline__ uint32_t packbf2(__nv_bfloat16 lo, __nv_bfloat16 hi) {
    return (uint32_t)__bfloat16_as_ushort(lo)
         | ((uint32_t)__bfloat16_as_ushort(hi) << 16);
}
__device__ __forceinline__ void split_bf(float v, __nv_bfloat16& h, __nv_bfloat16& l) {
    h = __float2bfloat16_rn(v);
    l = __float2bfloat16_rn(v - __bfloat162float(h));
}

// ---------------------------------------------------------------------------
// conv_a: fp32 x [M,1024] -> A'' [M][Ah | Al | Ah] bf16 row-major
// ---------------------------------------------------------------------------
__global__ __launch_bounds__(256) void conv_a_kernel(const float* __restrict__ src)
{
    const int m  = blockIdx.x;
    const int k4 = threadIdx.x << 2;
    float4 v = *(const float4*)(src + (size_t)m * E_ + k4);
    const float f[4] = {v.x, v.y, v.z, v.w};

    __nv_bfloat16 h[4], l[4];
#pragma unroll
    for (int j = 0; j < 4; j++) split_bf(f[j], h[j], l[j]);
    uint2 hi; hi.x = packbf2(h[0], h[1]); hi.y = packbf2(h[2], h[3]);
    uint2 lo; lo.x = packbf2(l[0], l[1]); lo.y = packbf2(l[2], l[3]);

    const size_t rb = (size_t)m * KPP_;
    *(uint2*)&g_at[rb + k4]        = hi;
    *(uint2*)&g_at[rb + 1024 + k4] = lo;
    *(uint2*)&g_at[rb + 2048 + k4] = hi;
}

// ---------------------------------------------------------------------------
// conv_w: W [1024][Ncols] fp32 -> W'' [n][Bh | Bh | Bl] bf16 (k contiguous)
// ---------------------------------------------------------------------------
__global__ __launch_bounds__(256) void conv_w_kernel(
    const float* __restrict__ W, int Ncols, int which)
{
    __nv_bfloat16* dst = which ? g_wpt : g_wqt;
    const int idx = blockIdx.x * 256 + threadIdx.x;
    const int n  = idx >> 8;
    const int k  = (idx & 255) << 2;
    if (n >= Ncols) return;

    float f[4];
#pragma unroll
    for (int j = 0; j < 4; j++)
        f[j] = W[(size_t)(k + j) * Ncols + n];

    __nv_bfloat16 h[4], l[4];
#pragma unroll
    for (int j = 0; j < 4; j++) split_bf(f[j], h[j], l[j]);
    uint2 hi; hi.x = packbf2(h[0], h[1]); hi.y = packbf2(h[2], h[3]);
    uint2 lo; lo.x = packbf2(l[0], l[1]); lo.y = packbf2(l[2], l[3]);

    const size_t rb = (size_t)n * KPP_;
    *(uint2*)&dst[rb + k]        = hi;
    *(uint2*)&dst[rb + 1024 + k] = hi;
    *(uint2*)&dst[rb + 2048 + k] = lo;
}

// ---------------------------------------------------------------------------
// HMMA GEMM: C[M, Ncols] = A''[M,3072] @ W''^T + bias
// CTA 128x128, K-step 64, 8 warps, 3-stage cp.async. Swizzled smem.
// mode 0: write Q/K hi-lo bf16 [B,H,N,D] and V^T hi-lo [B,H,D,N]
// mode 1: write fp32 out[M,E]
// ---------------------------------------------------------------------------
#define GEMM_SMEM (3 * 32768)

__device__ __forceinline__ void load_tile(
    uint32_t sbase, int stage, int ktile,
    const __nv_bfloat16* A, const __nv_bfloat16* Bt,
    int m0, int n0, int tid)
{
    const char* aSrc = (const char*)(A  + (size_t)m0 * KPP_ + ktile * 64);
    const char* bSrc = (const char*)(Bt + (size_t)n0 * KPP_ + ktile * 64);
    const uint32_t sa = sbase + stage * 32768;
    const uint32_t sbB = sa + 16384;
#pragma unroll
    for (int i = 0; i < 4; i++) {
        const int u = i * 256 + tid;
        const int r = u >> 3, c = u & 7;
        cp_async16(sa + r * 128 + ((c ^ (r & 7)) << 4),
                   aSrc + (size_t)r * (KPP_ * 2) + c * 16);
    }
#pragma unroll
    for (int i = 0; i < 4; i++) {
        const int u = i * 256 + tid;
        const int r = u >> 3, c = u & 7;
        cp_async16(sbB + r * 128 + ((c ^ (r & 7)) << 4),
                   bSrc + (size_t)r * (KPP_ * 2) + c * 16);
    }
    cp_commit();
}

__global__ __launch_bounds__(256) void hmma_gemm_kernel(
    const float* __restrict__ bias, float* __restrict__ out, int mode)
{
    extern __shared__ char smem[];
    const uint32_t sb = smem_u32(smem);

    const __nv_bfloat16* A  = g_at;
    const __nv_bfloat16* Bt = (mode == 0) ? g_wqt : g_wpt;

    const int tid  = threadIdx.x;
    const int lane = tid & 31, wid = tid >> 5;
    const int warp_m = wid & 1, warp_n = wid >> 1;
    const int m0 = blockIdx.y * 128, n0 = blockIdx.x * 128;

    float acc[4][4][4];
#pragma unroll
    for (int i = 0; i < 4; i++)
#pragma unroll
        for (int j = 0; j < 4; j++)
#pragma unroll
            for (int r = 0; r < 4; r++) acc[i][j][r] = 0.f;

    load_tile(sb, 0, 0, A, Bt, m0, n0, tid);
    load_tile(sb, 1, 1, A, Bt, m0, n0, tid);

    const int lane15 = lane & 15, lhalf = lane >> 4;

    for (int kt = 0; kt < KT_; kt++) {
        if (kt + 2 < KT_)
            load_tile(sb, (kt + 2) % 3, kt + 2, A, Bt, m0, n0, tid);
        else
            cp_commit();
        asm volatile("cp.async.wait_group 2;" ::: "memory");
        __syncthreads();

        const uint32_t sa  = sb + (kt % 3) * 32768;
        const uint32_t sbB = sa + 16384;
#pragma unroll
        for (int kk = 0; kk < 4; kk++) {
            const int kc = kk * 2 + lhalf;
            uint32_t a[4][4];
#pragma unroll
            for (int mi = 0; mi < 4; mi++) {
                const int r = warp_m * 64 + mi * 16 + lane15;
                ldmatrix_x4(a[mi], sa + r * 128 + ((kc ^ (r & 7)) << 4));
            }
            uint32_t bf[2][4];
#pragma unroll
            for (int ng = 0; ng < 2; ng++) {
                const int r = warp_n * 32 + ng * 16 + lane15;
                ldmatrix_x4(bf[ng], sbB + r * 128 + ((kc ^ (r & 7)) << 4));
            }
#pragma unroll
            for (int mi = 0; mi < 4; mi++)
#pragma unroll
                for (int nj = 0; nj < 4; nj++)
                    mma16816(acc[mi][nj], a[mi],
                             bf[nj >> 1][nj & 1], bf[nj >> 1][(nj & 1) + 2]);
        }
        __syncthreads();
    }

    // Epilogue
    const int mrow = m0 + warp_m * 64 + (lane >> 2);
    const int ncb  = n0 + warp_n * 32 + (lane & 3) * 2;
#pragma unroll
    for (int mi = 0; mi < 4; mi++) {
#pragma unroll
        for (int nj = 0; nj < 4; nj++) {
            const int c  = ncb + nj * 8;
            const float b0 = bias[c], b1 = bias[c + 1];
            const int r0 = mrow + mi * 16;
            float v00 = acc[mi][nj][0] + b0, v01 = acc[mi][nj][1] + b1;
            float v10 = acc[mi][nj][2] + b0, v11 = acc[mi][nj][3] + b1;
            if (mode == 1) {
                float2 p0; p0.x = v00; p0.y = v01;
                float2 p1; p1.x = v10; p1.y = v11;
                *(float2*)&out[(size_t)r0 * E_ + c] = p0;
                *(float2*)&out[(size_t)(r0 + 8) * E_ + c] = p1;
                continue;
            }
            // mode 0: split hi/lo and route
            __nv_bfloat16 h00, l00, h01, l01, h10, l10, h11, l11;
            split_bf(v00, h00, l00); split_bf(v01, h01, l01);
            split_bf(v10, h10, l10); split_bf(v11, h11, l11);
            const int sec = c >> 10, e = c & 1023;
            const int hh = e >> 6, dd = e & 63;
            const int bb = r0 >> 10, nn = r0 & 1023;   // r0+8 same block
            if (sec <= 1) {
                __nv_bfloat16* dh = sec == 0 ? g_qh : g_kh;
                __nv_bfloat16* dl = sec == 0 ? g_ql : g_kl;
                const size_t i0 = (((size_t)bb * H_ + hh) * N_ + nn) * D_ + dd;
                const size_t i1 = i0 + 8 * D_;
                *(uint32_t*)&dh[i0] = packbf2(h00, h01);
                *(uint32_t*)&dl[i0] = packbf2(l00, l01);
                *(uint32_t*)&dh[i1] = packbf2(h10, h11);
                *(uint32_t*)&dl[i1] = packbf2(l10, l11);
            } else {
                // V^T [B,H,D,N]: row = d, col = token
                const size_t i00 = (((size_t)bb * H_ + hh) * D_ + dd) * N_ + nn;
                g_vth[i00] = h00;          g_vtl[i00] = l00;
                g_vth[i00 + N_] = h01;     g_vtl[i00 + N_] = l01;       // d+1
                g_vth[i00 + 8] = h10;      g_vtl[i00 + 8] = l10;        // n+8
                g_vth[i00 + N_ + 8] = h11; g_vtl[i00 + N_ + 8] = l11;
            }
        }
    }
}

// ---------------------------------------------------------------------------
// Flash attention on HMMA. CTA = 64 q rows x one (b,h); 4 warps (16 q each).
// kv tiles of 64, 2-stage cp.async pipeline. 3-term bf16 splits for QK and PV.
// Epilogue writes A'' (hi|lo|hi) for the projection GEMM.
// ---------------------------------------------------------------------------
#define ATT_SMEM (2 * 32768)
// stage layout: Kh @0, Kl @8192, Vh @16384, Vl @24576 (each 64 rows x 128B)

__device__ __forceinline__ void att_load_tile(
    uint32_t st, int kv0,
    const __nv_bfloat16* kh, const __nv_bfloat16* kl,
    const __nv_bfloat16* vh, const __nv_bfloat16* vl, int tid)
{
#pragma unroll
    for (int i = 0; i < 4; i++) {
        const int u = i * 128 + tid;
        const int r = u >> 3, c = u & 7;
        const uint32_t soff = r * 128 + ((c ^ (r & 7)) << 4);
        cp_async16(st + soff,         (const char*)kh + (size_t)(kv0 + r) * 128 + c * 16);
        cp_async16(st + 8192 + soff,  (const char*)kl + (size_t)(kv0 + r) * 128 + c * 16);
        cp_async16(st + 16384 + soff, (const char*)vh + (size_t)r * 2048 + kv0 * 2 + c * 16);
        cp_async16(st + 24576 + soff, (const char*)vl + (size_t)r * 2048 + kv0 * 2 + c * 16);
    }
    cp_commit();
}

__global__ __launch_bounds__(128) void attn_hmma_kernel()
{
    extern __shared__ char smem[];
    const uint32_t sb = smem_u32(smem);

    const int tid = threadIdx.x;
    const int lane = tid & 31, w = tid >> 5;
    const int lane15 = lane & 15, lhalf = lane >> 4;
    const int q0 = blockIdx.x * 64;
    const int h  = blockIdx.y;
    const int b  = blockIdx.z;

    const size_t hb = (size_t)(b * H_ + h) * (N_ * D_);   // == B,H,D,N base too
    const __nv_bfloat16* qh = g_qh + hb;
    const __nv_bfloat16* ql = g_ql + hb;
    const __nv_bfloat16* kh = g_kh + hb;
    const __nv_bfloat16* kl = g_kl + hb;
    const __nv_bfloat16* vh = g_vth + hb;
    const __nv_bfloat16* vl = g_vtl + hb;

    // ---- load Q tile (hi->Kh area, lo->Kl area of stage 0), grab fragments
#pragma unroll
    for (int i = 0; i < 4; i++) {
        const int u = i * 128 + tid;
        const int r = u >> 3, c = u & 7;
        const uint32_t soff = r * 128 + ((c ^ (r & 7)) << 4);
        cp_async16(sb + soff,        (const char*)qh + (size_t)(q0 + r) * 128 + c * 16);
        cp_async16(sb + 8192 + soff, (const char*)ql + (size_t)(q0 + r) * 128 + c * 16);
    }
    cp_commit();
    asm volatile("cp.async.wait_group 0;" ::: "memory");
    __syncthreads();

    uint32_t qfh[4][4], qfl[4][4];
    {
        const int r = w * 16 + lane15;
#pragma unroll
        for (int t = 0; t < 4; t++) {
            const uint32_t soff = r * 128 + (((t * 2 + lhalf) ^ (r & 7)) << 4);
            ldmatrix_x4(qfh[t], sb + soff);
            ldmatrix_x4(qfl[t], sb + 8192 + soff);
        }
    }
    __syncthreads();

    // ---- state
    float mstate[2] = {-1e30f, -1e30f};
    float lstate[2] = {0.f, 0.f};
    float oacc[8][4];
#pragma unroll
    for (int j = 0; j < 8; j++)
#pragma unroll
        for (int r = 0; r < 4; r++) oacc[j][r] = 0.f;

    const float cexp = 0.18033688f;   // D^-0.5 * log2(e)

    // ---- pipeline prologue
    att_load_tile(sb, 0, kh, kl, vh, vl, tid);
    att_load_tile(sb + 32768, 64, kh, kl, vh, vl, tid);

    for (int t = 0; t < 16; t++) {
        asm volatile("cp.async.wait_group 1;" ::: "memory");
        __syncthreads();
        const uint32_t stK = sb + (t & 1) * 32768;
        const uint32_t stV = stK + 16384;

        // ---- S = Q K^T (3-term split)
        float sacc[8][4];
#pragma unroll
        for (int j = 0; j < 8; j++)
#pragma unroll
            for (int r = 0; r < 4; r++) sacc[j][r] = 0.f;

#pragma unroll
        for (int kvg = 0; kvg < 4; kvg++) {
            const int rb = kvg * 16 + lane15;
#pragma unroll
            for (int kk = 0; kk < 4; kk++) {
                const uint32_t soff = rb * 128 + (((kk * 2 + lhalf) ^ (rb & 7)) << 4);
                uint32_t bf[4];
                ldmatrix_x4(bf, stK + soff);               // Kh
                mma16816(sacc[2 * kvg],     qfh[kk], bf[0], bf[2]);
                mma16816(sacc[2 * kvg + 1], qfh[kk], bf[1], bf[3]);
                mma16816(sacc[2 * kvg],     qfl[kk], bf[0], bf[2]);
                mma16816(sacc[2 * kvg + 1], qfl[kk], bf[1], bf[3]);
                ldmatrix_x4(bf, stK + 8192 + soff);        // Kl
                mma16816(sacc[2 * kvg],     qfh[kk], bf[0], bf[2]);
                mma16816(sacc[2 * kvg + 1], qfh[kk], bf[1], bf[3]);
            }
        }

        // ---- fragment softmax (rows r = lane>>2 and r+8)
#pragma unroll
        for (int rr = 0; rr < 2; rr++) {
            float mx = -1e30f;
#pragma unroll
            for (int j = 0; j < 8; j++)
                mx = fmaxf(mx, fmaxf(sacc[j][rr * 2], sacc[j][rr * 2 + 1]));
            mx = fmaxf(mx, __shfl_xor_sync(0xffffffffu, mx, 1));
            mx = fmaxf(mx, __shfl_xor_sync(0xffffffffu, mx, 2));
            const float mnew  = fmaxf(mstate[rr], mx);
            const float alpha = exp2f((mstate[rr] - mnew) * cexp);
            mstate[rr] = mnew;
            float rs = 0.f;
#pragma unroll
            for (int j = 0; j < 8; j++) {
                const float p0 = exp2f((sacc[j][rr * 2]     - mnew) * cexp);
                const float p1 = exp2f((sacc[j][rr * 2 + 1] - mnew) * cexp);
                sacc[j][rr * 2] = p0; sacc[j][rr * 2 + 1] = p1;
                rs += p0 + p1;
            }
            rs += __shfl_xor_sync(0xffffffffu, rs, 1);
            rs += __shfl_xor_sync(0xffffffffu, rs, 2);
            lstate[rr] = lstate[rr] * alpha + rs;
#pragma unroll
            for (int j = 0; j < 8; j++) {
                oacc[j][rr * 2]     *= alpha;
                oacc[j][rr * 2 + 1] *= alpha;
            }
        }

        // ---- build P fragments in registers (A-frag layout == C-frag layout)
        uint32_t ph[4][4], pl[4][4];
#pragma unroll
        for (int kk = 0; kk < 4; kk++) {
#pragma unroll
            for (int q = 0; q < 4; q++) {
                const int tile = 2 * kk + (q >> 1);
                const int ri   = (q & 1) * 2;
                const float p0 = sacc[tile][ri], p1 = sacc[tile][ri + 1];
                __nv_bfloat16 h0, l0, h1, l1;
                split_bf(p0, h0, l0); split_bf(p1, h1, l1);
                ph[kk][q] = packbf2(h0, h1);
                pl[kk][q] = packbf2(l0, l1);
            }
        }

        // ---- O += P V (3-term split); B = V^T (n-major rows = d)
#pragma unroll
        for (int dg = 0; dg < 4; dg++) {
            const int rb = dg * 16 + lane15;
#pragma unroll
            for (int kk = 0; kk < 4; kk++) {
                const uint32_t soff = rb * 128 + (((kk * 2 + lhalf) ^ (rb & 7)) << 4);
                uint32_t bf[4];
                ldmatrix_x4(bf, stV + soff);               // Vh
                mma16816(oacc[2 * dg],     ph[kk], bf[0], bf[2]);
                mma16816(oacc[2 * dg + 1], ph[kk], bf[1], bf[3]);
                mma16816(oacc[2 * dg],     pl[kk], bf[0], bf[2]);
                mma16816(oacc[2 * dg + 1], pl[kk], bf[1], bf[3]);
                ldmatrix_x4(bf, stV + 8192 + soff);        // Vl
                mma16816(oacc[2 * dg],     ph[kk], bf[0], bf[2]);
                mma16816(oacc[2 * dg + 1], ph[kk], bf[1], bf[3]);
            }
        }

        __syncthreads();
        if (t + 2 < 16)
            att_load_tile(sb + (t & 1) * 32768, (t + 2) * 64, kh, kl, vh, vl, tid);
        else
            cp_commit();
    }

    // ---- epilogue: normalize, split hi/lo, write A'' rows for proj GEMM
    const float inv0 = 1.f / lstate[0];
    const float inv1 = 1.f / lstate[1];
    const int qrow = q0 + w * 16 + (lane >> 2);
    const size_t m0r = (size_t)(b * N_ + qrow) * KPP_;
    const size_t m1r = m0r + (size_t)8 * KPP_;
    const int colb = h * 64 + 2 * (lane & 3);
#pragma unroll
    for (int j = 0; j < 8; j++) {
        const int col = colb + 8 * j;
        {
            __nv_bfloat16 h0, l0, h1, l1;
            split_bf(oacc[j][0] * inv0, h0, l0);
            split_bf(oacc[j][1] * inv0, h1, l1);
            const uint32_t hi = packbf2(h0, h1), lo = packbf2(l0, l1);
            *(uint32_t*)&g_at[m0r + col]        = hi;
            *(uint32_t*)&g_at[m0r + 1024 + col] = lo;
            *(uint32_t*)&g_at[m0r + 2048 + col] = hi;
        }
        {
            __nv_bfloat16 h0, l0, h1, l1;
            split_bf(oacc[j][2] * inv1, h0, l0);
            split_bf(oacc[j][3] * inv1, h1, l1);
            const uint32_t hi = packbf2(h0, h1), lo = packbf2(l0, l1);
            *(uint32_t*)&g_at[m1r + col]        = hi;
            *(uint32_t*)&g_at[m1r + 1024 + col] = lo;
            *(uint32_t*)&g_at[m1r + 2048 + col] = hi;
        }
    }
}

// ---------------------------------------------------------------------------
extern "C" void kernel_launch(void* const* d_in, const int* in_sizes, int n_in,
                              void* d_out, int out_size)
{
    const float* x  = (const float*)d_in[0];   // [B,N,E]
    const float* Wq = (const float*)d_in[1];   // [E,3E]
    const float* bq = (const float*)d_in[2];   // [3E]
    const float* Wp = (const float*)d_in[3];   // [E,E]
    const float* bp = (const float*)d_in[4];   // [E]
    float* out = (float*)d_out;                // [B,N,E]

    cudaFuncSetAttribute(hmma_gemm_kernel,
                         cudaFuncAttributeMaxDynamicSharedMemorySize, GEMM_SMEM);
    cudaFuncSetAttribute(attn_hmma_kernel,
                         cudaFuncAttributeMaxDynamicSharedMemorySize, ATT_SMEM);

    // 1. conversions
    conv_a_kernel<<<M_, 256>>>(x);
    conv_w_kernel<<<QKV_N, 256>>>(Wq, QKV_N, 0);
    conv_w_kernel<<<E_, 256>>>(Wp, E_, 1);

    // 2. QKV GEMM (HMMA) -> bf16 hi/lo Q,K + transposed V
    hmma_gemm_kernel<<<dim3(QKV_N / 128, M_ / 128), 256, GEMM_SMEM>>>(bq, out, 0);

    // 3. attention (HMMA flash) -> writes A'' for projection
    attn_hmma_kernel<<<dim3(N_ / 64, H_, B_), 128, ATT_SMEM>>>();

    // 4. projection GEMM
    hmma_gemm_kernel<<<dim3(E_ / 128, M_ / 128), 256, GEMM_SMEM>>>(bp, out, 1);
}

// round 5
// speedup vs baseline: 2.7472x; 1.0179x over previous
#include <cuda_runtime.h>
#include <cuda_bf16.h>
#include <cstdint>

#define B_   16
#define N_   1024
#define E_   1024
#define H_   16
#define D_   64
#define M_   (B_ * N_)        // 16384
#define QKV_N (3 * E_)        // 3072
#define KPP_  (3 * E_)        // tripled K'' = 3072
#define KT_   (KPP_ / 64)     // 48 k-iters of 64

// ---------------------------------------------------------------------------
// Scratch (__device__ globals; no allocations anywhere)
// ---------------------------------------------------------------------------
static __device__ __align__(1024) __nv_bfloat16 g_qh[(size_t)B_ * H_ * N_ * D_];
static __device__ __align__(1024) __nv_bfloat16 g_ql[(size_t)B_ * H_ * N_ * D_];
static __device__ __align__(1024) __nv_bfloat16 g_kh[(size_t)B_ * H_ * N_ * D_];
static __device__ __align__(1024) __nv_bfloat16 g_kl[(size_t)B_ * H_ * N_ * D_];
static __device__ __align__(1024) __nv_bfloat16 g_vth[(size_t)B_ * H_ * D_ * N_];
static __device__ __align__(1024) __nv_bfloat16 g_vtl[(size_t)B_ * H_ * D_ * N_];
static __device__ __align__(1024) __nv_bfloat16 g_at [(size_t)M_ * KPP_];
static __device__ __align__(1024) __nv_bfloat16 g_wqt[(size_t)QKV_N * KPP_];
static __device__ __align__(1024) __nv_bfloat16 g_wpt[(size_t)E_ * KPP_];

// ---------------------------------------------------------------------------
// helpers
// ---------------------------------------------------------------------------
__device__ __forceinline__ uint32_t smem_u32(const void* p) {
    uint32_t a;
    asm("{ .reg .u64 t; cvta.to.shared.u64 t, %1; cvt.u32.u64 %0, t; }"
        : "=r"(a) : "l"(p));
    return a;
}
__device__ __forceinline__ void cp_async16(uint32_t dst, const void* src) {
    asm volatile("cp.async.cg.shared.global [%0], [%1], 16;"
                 :: "r"(dst), "l"(src));
}
__device__ __forceinline__ void cp_commit() {
    asm volatile("cp.async.commit_group;" ::: "memory");
}
__device__ __forceinline__ void ldmatrix_x4(uint32_t* d, uint32_t addr) {
    asm volatile("ldmatrix.sync.aligned.m8n8.x4.shared.b16 {%0,%1,%2,%3}, [%4];"
                 : "=r"(d[0]), "=r"(d[1]), "=r"(d[2]), "=r"(d[3]) : "r"(addr));
}
__device__ __forceinline__ void mma16816(float* c, const uint32_t* a,
                                         uint32_t b0, uint32_t b1) {
    asm volatile(
        "mma.sync.aligned.m16n8k16.row.col.f32.bf16.bf16.f32 "
        "{%0,%1,%2,%3}, {%4,%5,%6,%7}, {%8,%9}, {%0,%1,%2,%3};"
        : "+f"(c[0]), "+f"(c[1]), "+f"(c[2]), "+f"(c[3])
        : "r"(a[0]), "r"(a[1]), "r"(a[2]), "r"(a[3]), "r"(b0), "r"(b1));
}
__device__ __forceinline__ uint32_t packbf2(__nv_bfloat16 lo, __nv_bfloat16 hi) {
    return (uint32_t)__bfloat16_as_ushort(lo)
         | ((uint32_t)__bfloat16_as_ushort(hi) << 16);
}
__device__ __forceinline__ void split_bf(float v, __nv_bfloat16& h, __nv_bfloat16& l) {
    h = __float2bfloat16_rn(v);
    l = __float2bfloat16_rn(v - __bfloat162float(h));
}

// ---------------------------------------------------------------------------
// conv_a: fp32 x [M,1024] -> A'' [M][Ah | Al | Ah] bf16 row-major
// ---------------------------------------------------------------------------
__global__ __launch_bounds__(256) void conv_a_kernel(const float* __restrict__ src)
{
    const int m  = blockIdx.x;
    const int k4 = threadIdx.x << 2;
    float4 v = *(const float4*)(src + (size_t)m * E_ + k4);
    const float f[4] = {v.x, v.y, v.z, v.w};

    __nv_bfloat16 h[4], l[4];
#pragma unroll
    for (int j = 0; j < 4; j++) split_bf(f[j], h[j], l[j]);
    uint2 hi; hi.x = packbf2(h[0], h[1]); hi.y = packbf2(h[2], h[3]);
    uint2 lo; lo.x = packbf2(l[0], l[1]); lo.y = packbf2(l[2], l[3]);

    const size_t rb = (size_t)m * KPP_;
    *(uint2*)&g_at[rb + k4]        = hi;
    *(uint2*)&g_at[rb + 1024 + k4] = lo;
    *(uint2*)&g_at[rb + 2048 + k4] = hi;
}

// ---------------------------------------------------------------------------
// conv_w: W [1024][Ncols] fp32 -> W'' [n][Bh | Bh | Bl] bf16 (k contiguous)
// ---------------------------------------------------------------------------
__global__ __launch_bounds__(256) void conv_w_kernel(
    const float* __restrict__ W, int Ncols, int which)
{
    __nv_bfloat16* dst = which ? g_wpt : g_wqt;
    const int idx = blockIdx.x * 256 + threadIdx.x;
    const int n  = idx >> 8;
    const int k  = (idx & 255) << 2;
    if (n >= Ncols) return;

    float f[4];
#pragma unroll
    for (int j = 0; j < 4; j++)
        f[j] = W[(size_t)(k + j) * Ncols + n];

    __nv_bfloat16 h[4], l[4];
#pragma unroll
    for (int j = 0; j < 4; j++) split_bf(f[j], h[j], l[j]);
    uint2 hi; hi.x = packbf2(h[0], h[1]); hi.y = packbf2(h[2], h[3]);
    uint2 lo; lo.x = packbf2(l[0], l[1]); lo.y = packbf2(l[2], l[3]);

    const size_t rb = (size_t)n * KPP_;
    *(uint2*)&dst[rb + k]        = hi;
    *(uint2*)&dst[rb + 1024 + k] = hi;
    *(uint2*)&dst[rb + 2048 + k] = lo;
}

// ---------------------------------------------------------------------------
// HMMA GEMM: C[M, Ncols] = A''[M,3072] @ W''^T + bias
// CTA 128x128, K-step 64, **4 warps, warp tile 64x64**, 3-stage cp.async.
// MMA:ldmatrix ratio 4:1 (was 2.7:1).
// mode 0: write Q/K hi-lo bf16 [B,H,N,D] and V^T hi-lo [B,H,D,N]
// mode 1: write fp32 out[M,E]
// ---------------------------------------------------------------------------
#define GEMM_SMEM (3 * 32768)

__device__ __forceinline__ void load_tile(
    uint32_t sbase, int stage, int ktile,
    const __nv_bfloat16* A, const __nv_bfloat16* Bt,
    int m0, int n0, int tid)
{
    const char* aSrc = (const char*)(A  + (size_t)m0 * KPP_ + ktile * 64);
    const char* bSrc = (const char*)(Bt + (size_t)n0 * KPP_ + ktile * 64);
    const uint32_t sa = sbase + stage * 32768;
    const uint32_t sbB = sa + 16384;
#pragma unroll
    for (int i = 0; i < 8; i++) {
        const int u = i * 128 + tid;
        const int r = u >> 3, c = u & 7;
        cp_async16(sa + r * 128 + ((c ^ (r & 7)) << 4),
                   aSrc + (size_t)r * (KPP_ * 2) + c * 16);
    }
#pragma unroll
    for (int i = 0; i < 8; i++) {
        const int u = i * 128 + tid;
        const int r = u >> 3, c = u & 7;
        cp_async16(sbB + r * 128 + ((c ^ (r & 7)) << 4),
                   bSrc + (size_t)r * (KPP_ * 2) + c * 16);
    }
    cp_commit();
}

__global__ __launch_bounds__(128) void hmma_gemm_kernel(
    const float* __restrict__ bias, float* __restrict__ out, int mode)
{
    extern __shared__ char smem[];
    const uint32_t sb = smem_u32(smem);

    const __nv_bfloat16* A  = g_at;
    const __nv_bfloat16* Bt = (mode == 0) ? g_wqt : g_wpt;

    const int tid  = threadIdx.x;
    const int lane = tid & 31, wid = tid >> 5;
    const int warp_m = wid & 1, warp_n = wid >> 1;
    const int m0 = blockIdx.y * 128, n0 = blockIdx.x * 128;

    float acc[4][8][4];
#pragma unroll
    for (int i = 0; i < 4; i++)
#pragma unroll
        for (int j = 0; j < 8; j++)
#pragma unroll
            for (int r = 0; r < 4; r++) acc[i][j][r] = 0.f;

    load_tile(sb, 0, 0, A, Bt, m0, n0, tid);
    load_tile(sb, 1, 1, A, Bt, m0, n0, tid);

    const int lane15 = lane & 15, lhalf = lane >> 4;

    for (int kt = 0; kt < KT_; kt++) {
        if (kt + 2 < KT_)
            load_tile(sb, (kt + 2) % 3, kt + 2, A, Bt, m0, n0, tid);
        else
            cp_commit();
        asm volatile("cp.async.wait_group 2;" ::: "memory");
        __syncthreads();

        const uint32_t sa  = sb + (kt % 3) * 32768;
        const uint32_t sbB = sa + 16384;
#pragma unroll
        for (int kk = 0; kk < 4; kk++) {
            const int kc = kk * 2 + lhalf;
            uint32_t a[4][4];
#pragma unroll
            for (int mi = 0; mi < 4; mi++) {
                const int r = warp_m * 64 + mi * 16 + lane15;
                ldmatrix_x4(a[mi], sa + r * 128 + ((kc ^ (r & 7)) << 4));
            }
            uint32_t bf[4][4];
#pragma unroll
            for (int ng = 0; ng < 4; ng++) {
                const int r = warp_n * 64 + ng * 16 + lane15;
                ldmatrix_x4(bf[ng], sbB + r * 128 + ((kc ^ (r & 7)) << 4));
            }
#pragma unroll
            for (int mi = 0; mi < 4; mi++)
#pragma unroll
                for (int nj = 0; nj < 8; nj++)
                    mma16816(acc[mi][nj], a[mi],
                             bf[nj >> 1][nj & 1], bf[nj >> 1][(nj & 1) + 2]);
        }
        __syncthreads();
    }

    // Epilogue
    const int mrow = m0 + warp_m * 64 + (lane >> 2);
    const int ncb  = n0 + warp_n * 64 + (lane & 3) * 2;
#pragma unroll
    for (int mi = 0; mi < 4; mi++) {
#pragma unroll
        for (int nj = 0; nj < 8; nj++) {
            const int c  = ncb + nj * 8;
            const float b0 = bias[c], b1 = bias[c + 1];
            const int r0 = mrow + mi * 16;
            float v00 = acc[mi][nj][0] + b0, v01 = acc[mi][nj][1] + b1;
            float v10 = acc[mi][nj][2] + b0, v11 = acc[mi][nj][3] + b1;
            if (mode == 1) {
                float2 p0; p0.x = v00; p0.y = v01;
                float2 p1; p1.x = v10; p1.y = v11;
                *(float2*)&out[(size_t)r0 * E_ + c] = p0;
                *(float2*)&out[(size_t)(r0 + 8) * E_ + c] = p1;
                continue;
            }
            __nv_bfloat16 h00, l00, h01, l01, h10, l10, h11, l11;
            split_bf(v00, h00, l00); split_bf(v01, h01, l01);
            split_bf(v10, h10, l10); split_bf(v11, h11, l11);
            const int sec = c >> 10, e = c & 1023;
            const int hh = e >> 6, dd = e & 63;
            const int bb = r0 >> 10, nn = r0 & 1023;
            if (sec <= 1) {
                __nv_bfloat16* dh = sec == 0 ? g_qh : g_kh;
                __nv_bfloat16* dl = sec == 0 ? g_ql : g_kl;
                const size_t i0 = (((size_t)bb * H_ + hh) * N_ + nn) * D_ + dd;
                const size_t i1 = i0 + 8 * D_;
                *(uint32_t*)&dh[i0] = packbf2(h00, h01);
                *(uint32_t*)&dl[i0] = packbf2(l00, l01);
                *(uint32_t*)&dh[i1] = packbf2(h10, h11);
                *(uint32_t*)&dl[i1] = packbf2(l10, l11);
            } else {
                const size_t i00 = (((size_t)bb * H_ + hh) * D_ + dd) * N_ + nn;
                g_vth[i00] = h00;          g_vtl[i00] = l00;
                g_vth[i00 + N_] = h01;     g_vtl[i00 + N_] = l01;
                g_vth[i00 + 8] = h10;      g_vtl[i00 + 8] = l10;
                g_vth[i00 + N_ + 8] = h11; g_vtl[i00 + N_ + 8] = l11;
            }
        }
    }
}

// ---------------------------------------------------------------------------
// Flash attention on HMMA (unchanged from round 4).
// ---------------------------------------------------------------------------
#define ATT_SMEM (2 * 32768)

__device__ __forceinline__ void att_load_tile(
    uint32_t st, int kv0,
    const __nv_bfloat16* kh, const __nv_bfloat16* kl,
    const __nv_bfloat16* vh, const __nv_bfloat16* vl, int tid)
{
#pragma unroll
    for (int i = 0; i < 4; i++) {
        const int u = i * 128 + tid;
        const int r = u >> 3, c = u & 7;
        const uint32_t soff = r * 128 + ((c ^ (r & 7)) << 4);
        cp_async16(st + soff,         (const char*)kh + (size_t)(kv0 + r) * 128 + c * 16);
        cp_async16(st + 8192 + soff,  (const char*)kl + (size_t)(kv0 + r) * 128 + c * 16);
        cp_async16(st + 16384 + soff, (const char*)vh + (size_t)r * 2048 + kv0 * 2 + c * 16);
        cp_async16(st + 24576 + soff, (const char*)vl + (size_t)r * 2048 + kv0 * 2 + c * 16);
    }
    cp_commit();
}

__global__ __launch_bounds__(128) void attn_hmma_kernel()
{
    extern __shared__ char smem[];
    const uint32_t sb = smem_u32(smem);

    const int tid = threadIdx.x;
    const int lane = tid & 31, w = tid >> 5;
    const int lane15 = lane & 15, lhalf = lane >> 4;
    const int q0 = blockIdx.x * 64;
    const int h  = blockIdx.y;
    const int b  = blockIdx.z;

    const size_t hb = (size_t)(b * H_ + h) * (N_ * D_);
    const __nv_bfloat16* qh = g_qh + hb;
    const __nv_bfloat16* ql = g_ql + hb;
    const __nv_bfloat16* kh = g_kh + hb;
    const __nv_bfloat16* kl = g_kl + hb;
    const __nv_bfloat16* vh = g_vth + hb;
    const __nv_bfloat16* vl = g_vtl + hb;

#pragma unroll
    for (int i = 0; i < 4; i++) {
        const int u = i * 128 + tid;
        const int r = u >> 3, c = u & 7;
        const uint32_t soff = r * 128 + ((c ^ (r & 7)) << 4);
        cp_async16(sb + soff,        (const char*)qh + (size_t)(q0 + r) * 128 + c * 16);
        cp_async16(sb + 8192 + soff, (const char*)ql + (size_t)(q0 + r) * 128 + c * 16);
    }
    cp_commit();
    asm volatile("cp.async.wait_group 0;" ::: "memory");
    __syncthreads();

    uint32_t qfh[4][4], qfl[4][4];
    {
        const int r = w * 16 + lane15;
#pragma unroll
        for (int t = 0; t < 4; t++) {
            const uint32_t soff = r * 128 + (((t * 2 + lhalf) ^ (r & 7)) << 4);
            ldmatrix_x4(qfh[t], sb + soff);
            ldmatrix_x4(qfl[t], sb + 8192 + soff);
        }
    }
    __syncthreads();

    float mstate[2] = {-1e30f, -1e30f};
    float lstate[2] = {0.f, 0.f};
    float oacc[8][4];
#pragma unroll
    for (int j = 0; j < 8; j++)
#pragma unroll
        for (int r = 0; r < 4; r++) oacc[j][r] = 0.f;

    const float cexp = 0.18033688f;   // D^-0.5 * log2(e)

    att_load_tile(sb, 0, kh, kl, vh, vl, tid);
    att_load_tile(sb + 32768, 64, kh, kl, vh, vl, tid);

    for (int t = 0; t < 16; t++) {
        asm volatile("cp.async.wait_group 1;" ::: "memory");
        __syncthreads();
        const uint32_t stK = sb + (t & 1) * 32768;
        const uint32_t stV = stK + 16384;

        float sacc[8][4];
#pragma unroll
        for (int j = 0; j < 8; j++)
#pragma unroll
            for (int r = 0; r < 4; r++) sacc[j][r] = 0.f;

#pragma unroll
        for (int kvg = 0; kvg < 4; kvg++) {
            const int rb = kvg * 16 + lane15;
#pragma unroll
            for (int kk = 0; kk < 4; kk++) {
                const uint32_t soff = rb * 128 + (((kk * 2 + lhalf) ^ (rb & 7)) << 4);
                uint32_t bf[4];
                ldmatrix_x4(bf, stK + soff);
                mma16816(sacc[2 * kvg],     qfh[kk], bf[0], bf[2]);
                mma16816(sacc[2 * kvg + 1], qfh[kk], bf[1], bf[3]);
                mma16816(sacc[2 * kvg],     qfl[kk], bf[0], bf[2]);
                mma16816(sacc[2 * kvg + 1], qfl[kk], bf[1], bf[3]);
                ldmatrix_x4(bf, stK + 8192 + soff);
                mma16816(sacc[2 * kvg],     qfh[kk], bf[0], bf[2]);
                mma16816(sacc[2 * kvg + 1], qfh[kk], bf[1], bf[3]);
            }
        }

#pragma unroll
        for (int rr = 0; rr < 2; rr++) {
            float mx = -1e30f;
#pragma unroll
            for (int j = 0; j < 8; j++)
                mx = fmaxf(mx, fmaxf(sacc[j][rr * 2], sacc[j][rr * 2 + 1]));
            mx = fmaxf(mx, __shfl_xor_sync(0xffffffffu, mx, 1));
            mx = fmaxf(mx, __shfl_xor_sync(0xffffffffu, mx, 2));
            const float mnew  = fmaxf(mstate[rr], mx);
            const float alpha = exp2f((mstate[rr] - mnew) * cexp);
            mstate[rr] = mnew;
            float rs = 0.f;
#pragma unroll
            for (int j = 0; j < 8; j++) {
                const float p0 = exp2f((sacc[j][rr * 2]     - mnew) * cexp);
                const float p1 = exp2f((sacc[j][rr * 2 + 1] - mnew) * cexp);
                sacc[j][rr * 2] = p0; sacc[j][rr * 2 + 1] = p1;
                rs += p0 + p1;
            }
            rs += __shfl_xor_sync(0xffffffffu, rs, 1);
            rs += __shfl_xor_sync(0xffffffffu, rs, 2);
            lstate[rr] = lstate[rr] * alpha + rs;
#pragma unroll
            for (int j = 0; j < 8; j++) {
                oacc[j][rr * 2]     *= alpha;
                oacc[j][rr * 2 + 1] *= alpha;
            }
        }

        uint32_t ph[4][4], pl[4][4];
#pragma unroll
        for (int kk = 0; kk < 4; kk++) {
#pragma unroll
            for (int q = 0; q < 4; q++) {
                const int tile = 2 * kk + (q >> 1);
                const int ri   = (q & 1) * 2;
                const float p0 = sacc[tile][ri], p1 = sacc[tile][ri + 1];
                __nv_bfloat16 h0, l0, h1, l1;
                split_bf(p0, h0, l0); split_bf(p1, h1, l1);
                ph[kk][q] = packbf2(h0, h1);
                pl[kk][q] = packbf2(l0, l1);
            }
        }

#pragma unroll
        for (int dg = 0; dg < 4; dg++) {
            const int rb = dg * 16 + lane15;
#pragma unroll
            for (int kk = 0; kk < 4; kk++) {
                const uint32_t soff = rb * 128 + (((kk * 2 + lhalf) ^ (rb & 7)) << 4);
                uint32_t bf[4];
                ldmatrix_x4(bf, stV + soff);
                mma16816(oacc[2 * dg],     ph[kk], bf[0], bf[2]);
                mma16816(oacc[2 * dg + 1], ph[kk], bf[1], bf[3]);
                mma16816(oacc[2 * dg],     pl[kk], bf[0], bf[2]);
                mma16816(oacc[2 * dg + 1], pl[kk], bf[1], bf[3]);
                ldmatrix_x4(bf, stV + 8192 + soff);
                mma16816(oacc[2 * dg],     ph[kk], bf[0], bf[2]);
                mma16816(oacc[2 * dg + 1], ph[kk], bf[1], bf[3]);
            }
        }

        __syncthreads();
        if (t + 2 < 16)
            att_load_tile(sb + (t & 1) * 32768, (t + 2) * 64, kh, kl, vh, vl, tid);
        else
            cp_commit();
    }

    const float inv0 = 1.f / lstate[0];
    const float inv1 = 1.f / lstate[1];
    const int qrow = q0 + w * 16 + (lane >> 2);
    const size_t m0r = (size_t)(b * N_ + qrow) * KPP_;
    const size_t m1r = m0r + (size_t)8 * KPP_;
    const int colb = h * 64 + 2 * (lane & 3);
#pragma unroll
    for (int j = 0; j < 8; j++) {
        const int col = colb + 8 * j;
        {
            __nv_bfloat16 h0, l0, h1, l1;
            split_bf(oacc[j][0] * inv0, h0, l0);
            split_bf(oacc[j][1] * inv0, h1, l1);
            const uint32_t hi = packbf2(h0, h1), lo = packbf2(l0, l1);
            *(uint32_t*)&g_at[m0r + col]        = hi;
            *(uint32_t*)&g_at[m0r + 1024 + col] = lo;
            *(uint32_t*)&g_at[m0r + 2048 + col] = hi;
        }
        {
            __nv_bfloat16 h0, l0, h1, l1;
            split_bf(oacc[j][2] * inv1, h0, l0);
            split_bf(oacc[j][3] * inv1, h1, l1);
            const uint32_t hi = packbf2(h0, h1), lo = packbf2(l0, l1);
            *(uint32_t*)&g_at[m1r + col]        = hi;
            *(uint32_t*)&g_at[m1r + 1024 + col] = lo;
            *(uint32_t*)&g_at[m1r + 2048 + col] = hi;
        }
    }
}

// ---------------------------------------------------------------------------
extern "C" void kernel_launch(void* const* d_in, const int* in_sizes, int n_in,
                              void* d_out, int out_size)
{
    const float* x  = (const float*)d_in[0];
    const float* Wq = (const float*)d_in[1];
    const float* bq = (const float*)d_in[2];
    const float* Wp = (const float*)d_in[3];
    const float* bp = (const float*)d_in[4];
    float* out = (float*)d_out;

    cudaFuncSetAttribute(hmma_gemm_kernel,
                         cudaFuncAttributeMaxDynamicSharedMemorySize, GEMM_SMEM);
    cudaFuncSetAttribute(attn_hmma_kernel,
                         cudaFuncAttributeMaxDynamicSharedMemorySize, ATT_SMEM);

    conv_a_kernel<<<M_, 256>>>(x);
    conv_w_kernel<<<QKV_N, 256>>>(Wq, QKV_N, 0);
    conv_w_kernel<<<E_, 256>>>(Wp, E_, 1);

    hmma_gemm_kernel<<<dim3(QKV_N / 128, M_ / 128), 128, GEMM_SMEM>>>(bq, out, 0);

    attn_hmma_kernel<<<dim3(N_ / 64, H_, B_), 128, ATT_SMEM>>>();

    hmma_gemm_kernel<<<dim3(E_ / 128, M_ / 128), 128, GEMM_SMEM>>>(bp, out, 1);
}